// round 4
// baseline (speedup 1.0000x reference)
#include <cuda_runtime.h>
#include <math.h>

#define NB 4
#define NS 256
#define ND 300
#define NM (NB*NS)   // 1024 rows
#define NK 300
#define N3 (3*ND)    // 900: dep' | head'(+b1) | g1(+b_f)
#define CC 5.0f
#define IG 2

// weight math constants: w ∝ exp(C*tanh(x/C)) = e^C * 2^(K2 / (1 + 2^(x*K_PRE)))
#define K_PRE 0.5770780163555854f     //  2*log2(e)/C
#define K2   -14.426950408889634f     // -2*C*log2(e)

// Scratch (static device globals — no allocation allowed)
__device__ float g_rep[NM*ND];
__device__ float g_dhg[NM*N3];
__device__ float g_attn[NM*ND];
__device__ float g_p0[NM*ND];
__device__ float g_p1[NM*ND];

#define BM 64
#define BN 64
#define BK 20        // 300 = 15 * 20
#define LPT 5        // loads/thread/tile: 64*20/256

typedef unsigned long long ull;

// ---------------- packed f32x2 helpers (FFMA2: 2x fp32 FMA rate) ------------
__device__ __forceinline__ ull pack2(float x, float y){
    ull r; asm("mov.b64 %0, {%1,%2};" : "=l"(r) : "f"(x), "f"(y)); return r;
}
__device__ __forceinline__ void ffma2(ull& d, ull a, ull b){
    asm("fma.rn.f32x2 %0, %1, %2, %0;" : "+l"(d) : "l"(a), "l"(b));
}
__device__ __forceinline__ float2 unpk(ull v){
    float2 r; asm("mov.b64 {%0,%1}, %2;" : "=f"(r.x), "=f"(r.y) : "l"(v)); return r;
}
__device__ __forceinline__ float ex2a(float x){ float y; asm("ex2.approx.f32 %0,%1;" : "=f"(y):"f"(x)); return y; }
__device__ __forceinline__ float rcpa(float x){ float y; asm("rcp.approx.f32 %0,%1;" : "=f"(y):"f"(x)); return y; }

// softmax weight (e^C factor dropped; cancels in normalization). 3 MUFU, 5 instr.
__device__ __forceinline__ float wfun(float xp)   // xp = dep' + hb' (pre-scaled)
{
    float e2 = ex2a(xp);
    float r  = rcpa(e2 + 1.f);
    return ex2a(K2 * r);
}

// 64x64 tile GEMM, C[m,n] += A[m,k]*W[n,k]. Double-buffered smem.
// A-tile stored DUPLICATED-PACKED (f32x2 (v,v)) so inner loop is
// 2xLDS.128(A) + 1xLDS.128(B) + 8xFFMA2 per k.
__device__ __forceinline__ void gemm_core(const float* __restrict__ A,
                                          const float* __restrict__ W,
                                          int m0, int n0, int kstart, int niter,
                                          ull (&acc)[4][2])
{
    __shared__ __align__(16) ull   As[2][BK][BM];
    __shared__ __align__(16) float Bs[2][BK][BN+4];
    const int tid = threadIdx.x;
    const int tx = tid & 15, ty = tid >> 4;

    #pragma unroll
    for (int e = 0; e < LPT; ++e) {
        int idx = tid + e*256;
        int r = idx / BK, c = idx - r*BK;
        float va = A[(m0 + r)*NK + kstart + c];
        As[0][c][r] = pack2(va, va);
        int gn = n0 + r;
        Bs[0][c][r] = (gn < ND) ? W[gn*NK + kstart + c] : 0.f;
    }
    __syncthreads();

    int buf = 0;
    for (int it = 0; it < niter; ++it) {
        const bool has_next = (it + 1 < niter);
        float ra[LPT], rb[LPT];
        if (has_next) {
            int kn = kstart + (it + 1)*BK;
            #pragma unroll
            for (int e = 0; e < LPT; ++e) {
                int idx = tid + e*256;
                int r = idx / BK, c = idx - r*BK;
                ra[e] = A[(m0 + r)*NK + kn + c];
                int gn = n0 + r;
                rb[e] = (gn < ND) ? W[gn*NK + kn + c] : 0.f;
            }
        }
        #pragma unroll
        for (int k = 0; k < BK; ++k) {
            const ulonglong2 a01 = *(const ulonglong2*)&As[buf][k][ty*4];
            const ulonglong2 a23 = *(const ulonglong2*)&As[buf][k][ty*4 + 2];
            const ulonglong2 bb  = *(const ulonglong2*)&Bs[buf][k][tx*4];
            ffma2(acc[0][0], a01.x, bb.x); ffma2(acc[0][1], a01.x, bb.y);
            ffma2(acc[1][0], a01.y, bb.x); ffma2(acc[1][1], a01.y, bb.y);
            ffma2(acc[2][0], a23.x, bb.x); ffma2(acc[2][1], a23.x, bb.y);
            ffma2(acc[3][0], a23.y, bb.x); ffma2(acc[3][1], a23.y, bb.y);
        }
        if (has_next) {
            __syncthreads();
            #pragma unroll
            for (int e = 0; e < LPT; ++e) {
                int idx = tid + e*256;
                int r = idx / BK, c = idx - r*BK;
                As[buf^1][c][r] = pack2(ra[e], ra[e]);
                Bs[buf^1][c][r] = rb[e];
            }
            __syncthreads();
            buf ^= 1;
        }
    }
}

// ---- P1: rep partial GEMM, split-K -----------------------------------------
__global__ void __launch_bounds__(256)
gemm_rep_split(const float* __restrict__ A, const float* __restrict__ W)
{
    const int m0 = blockIdx.y * BM, n0 = blockIdx.x * BN;
    const int z = blockIdx.z;
    float* __restrict__ dst = z ? g_p1 : g_p0;
    ull acc[4][2] = {};
    gemm_core(A, W, m0, n0, z ? 160 : 0, z ? 7 : 8, acc);
    const int tx = threadIdx.x & 15, ty = threadIdx.x >> 4;
    #pragma unroll
    for (int p = 0; p < 4; ++p) {
        int m = m0 + ty*4 + p;
        #pragma unroll
        for (int qq = 0; qq < 2; ++qq) {
            float2 v = unpk(acc[p][qq]);
            int n = n0 + tx*4 + qq*2;
            if (n < ND)     dst[m*ND + n]     = v.x;
            if (n + 1 < ND) dst[m*ND + n + 1] = v.y;
        }
    }
}

// ---- P1b: g_rep = elu(p0 + p1 + b_fc) --------------------------------------
__global__ void __launch_bounds__(256)
finish_rep(const float* __restrict__ bias)
{
    int idx = blockIdx.x * 256 + threadIdx.x;
    if (idx >= NM*ND) return;
    int n = idx % ND;
    float v = g_p0[idx] + g_p1[idx] + bias[n];
    g_rep[idx] = (v > 0.f) ? v : expm1f(v);
}

// ---- P2: dep'/head'/gate1 GEMM (z selects matrix; dep/head pre-scaled) -----
__global__ void __launch_bounds__(256)
gemm_triple(const float* __restrict__ W1, const float* __restrict__ W2,
            const float* __restrict__ Wf1, const float* __restrict__ b1,
            const float* __restrict__ bf)
{
    const int m0 = blockIdx.y * BM, n0 = blockIdx.x * BN;
    const int z = blockIdx.z;
    const float* W = (z == 0) ? W1 : ((z == 1) ? W2 : Wf1);
    ull acc[4][2] = {};
    gemm_core(g_rep, W, m0, n0, 0, 15, acc);
    const int tx = threadIdx.x & 15, ty = threadIdx.x >> 4;
    #pragma unroll
    for (int p = 0; p < 4; ++p) {
        int m = m0 + ty*4 + p;
        #pragma unroll
        for (int qq = 0; qq < 2; ++qq) {
            float2 v = unpk(acc[p][qq]);
            int n = n0 + tx*4 + qq*2;
            #pragma unroll
            for (int h = 0; h < 2; ++h) {
                int nn = n + h;
                if (nn < ND) {
                    float val = (h == 0) ? v.x : v.y;
                    if (z == 0)      val  = val * K_PRE;              // dep'
                    else if (z == 1) val  = (val + b1[nn]) * K_PRE;   // head'
                    else             val += bf[nn];                   // g1
                    g_dhg[m*N3 + z*ND + nn] = val;
                }
            }
        }
    }
}

// ---- P3: attention (IG=2, compacted valid-j list, j x2 unroll) -------------
__global__ void __launch_bounds__(320)
attn_kernel(const int* __restrict__ rmask)
{
    const int b = blockIdx.y;
    const int i0 = blockIdx.x * IG;
    const int t = threadIdx.x;

    __shared__ __align__(8) int jlist[NS];
    __shared__ int wcnt[8];
    __shared__ int nvalid_s;

    bool v = false;
    unsigned bal = 0;
    if (t < NS) {
        v = (t > i0) && (rmask[b*NS + t] != 0);
        bal = __ballot_sync(0xFFFFFFFFu, v);
        if ((t & 31) == 0) wcnt[t >> 5] = __popc(bal);
    }
    __syncthreads();
    if (t == 0) {
        int a = 0;
        #pragma unroll
        for (int k = 0; k < 8; ++k) { int c = wcnt[k]; wcnt[k] = a; a += c; }
        nvalid_s = a;
    }
    __syncthreads();
    if (t < NS && v) {
        int pos = wcnt[t >> 5] + __popc(bal & ((1u << (t & 31)) - 1u));
        jlist[pos] = t;
    }
    __syncthreads();

    const int nvalid = nvalid_s;
    if (t >= ND) return;

    const float hb0 = g_dhg[(size_t)(b*NS + i0    )*N3 + ND + t];  // head' i0
    const float hb1 = g_dhg[(size_t)(b*NS + i0 + 1)*N3 + ND + t];  // head' i0+1
    const float* __restrict__ dep_base = g_dhg + (size_t)(b*NS)*N3 + t;
    const float* __restrict__ rep_base = g_rep + (size_t)(b*NS)*ND + t;

    float s0 = 0.f, w0 = 0.f, s1 = 0.f, w1 = 0.f;
    int idx = 0;
    for (; idx + 2 <= nvalid; idx += 2) {
        int2 jj = *(const int2*)&jlist[idx];
        float dj0 = dep_base[jj.x*N3], dj1 = dep_base[jj.y*N3];
        float rv0 = rep_base[jj.x*ND], rv1 = rep_base[jj.y*ND];
        float e00 = wfun(dj0 + hb0);
        float e01 = wfun(dj1 + hb0);
        float e10 = wfun(dj0 + hb1);
        float e11 = wfun(dj1 + hb1);
        s0 += e00 + e01;
        w0 = fmaf(e00, rv0, fmaf(e01, rv1, w0));
        s1 += e10 + e11;
        w1 = fmaf(e10, rv0, fmaf(e11, rv1, w1));
    }
    if (idx < nvalid) {
        int j0 = jlist[idx];
        float dj0 = dep_base[j0*N3];
        float rv0 = rep_base[j0*ND];
        float e00 = wfun(dj0 + hb0);
        float e10 = wfun(dj0 + hb1);
        s0 += e00;  w0 = fmaf(e00, rv0, w0);
        s1 += e10;  w1 = fmaf(e10, rv0, w1);
    }
    // i1 = i0+1 must exclude j == i0+1 (only possibly-invalid entry = jlist[0])
    if (nvalid > 0 && jlist[0] == i0 + 1) {
        float dj0 = dep_base[(i0 + 1)*N3];
        float rv0 = rep_base[(i0 + 1)*ND];
        float e10 = wfun(dj0 + hb1);
        s1 -= e10;  w1 = fmaf(-e10, rv0, w1);
    }
    float d0 = s0 + ((s0 == 0.f) ? 1.f : 0.f) + 1e-20f;
    float d1 = s1 + ((s1 == 0.f) ? 1.f : 0.f) + 1e-20f;
    g_attn[(size_t)(b*NS + i0    )*ND + t] = w0 / d0;
    g_attn[(size_t)(b*NS + i0 + 1)*ND + t] = w1 / d1;
}

// ---- P4: attn @ W_f2^T, split-K partials -----------------------------------
__global__ void __launch_bounds__(256)
gemm_final_split(const float* __restrict__ Wf2)
{
    const int m0 = blockIdx.y * BM, n0 = blockIdx.x * BN;
    const int z = blockIdx.z;
    float* __restrict__ dst = z ? g_p1 : g_p0;
    ull acc[4][2] = {};
    gemm_core(g_attn, Wf2, m0, n0, z ? 160 : 0, z ? 7 : 8, acc);
    const int tx = threadIdx.x & 15, ty = threadIdx.x >> 4;
    #pragma unroll
    for (int p = 0; p < 4; ++p) {
        int m = m0 + ty*4 + p;
        #pragma unroll
        for (int qq = 0; qq < 2; ++qq) {
            float2 v = unpk(acc[p][qq]);
            int n = n0 + tx*4 + qq*2;
            if (n < ND)     dst[m*ND + n]     = v.x;
            if (n + 1 < ND) dst[m*ND + n + 1] = v.y;
        }
    }
}

// ---- P4b: gate + blend + mask ----------------------------------------------
__global__ void __launch_bounds__(256)
final_epi(const int* __restrict__ rmask, float* __restrict__ out)
{
    int idx = blockIdx.x * 256 + threadIdx.x;
    if (idx >= NM*ND) return;
    int m = idx / ND, n = idx - m*ND;
    float vv = g_p0[idx] + g_p1[idx] + g_dhg[m*N3 + 2*ND + n];  // + g1 (b_f folded)
    float gate = 1.f / (1.f + __expf(-vv));
    float r = g_rep[idx];
    float a = g_attn[idx];
    out[idx] = (gate*r + (1.f - gate)*a) * (float)rmask[m];
}

extern "C" void kernel_launch(void* const* d_in, const int* in_sizes, int n_in,
                              void* d_out, int out_size)
{
    const float* inputs = (const float*)d_in[0];
    const int*   rmask  = (const int*)d_in[1];
    const float* W_fc   = (const float*)d_in[2];
    const float* b_fc   = (const float*)d_in[3];
    const float* W1     = (const float*)d_in[4];
    const float* W2     = (const float*)d_in[5];
    const float* b1     = (const float*)d_in[6];
    const float* W_f1   = (const float*)d_in[7];
    const float* W_f2   = (const float*)d_in[8];
    const float* b_f    = (const float*)d_in[9];
    float* out = (float*)d_out;

    dim3 blk(256);
    const int eBlocks = (NM*ND + 255) / 256;

    gemm_rep_split  <<<dim3(5, 16, 2), blk>>>(inputs, W_fc);
    finish_rep      <<<eBlocks, blk>>>(b_fc);
    gemm_triple     <<<dim3(5, 16, 3), blk>>>(W1, W2, W_f1, b1, b_f);
    attn_kernel     <<<dim3(NS/IG, NB), 320>>>(rmask);
    gemm_final_split<<<dim3(5, 16, 2), blk>>>(W_f2);
    final_epi       <<<eBlocks, blk>>>(rmask, out);
}

// round 5
// speedup vs baseline: 1.6016x; 1.6016x over previous
#include <cuda_runtime.h>
#include <math.h>

#define NB 4
#define NS 256
#define ND 300
#define NM (NB*NS)   // 1024 rows
#define NK 300
#define N3 (3*ND)    // 900: pd | ph | g1(+b_f)
#define CC 5.0f
#define IG 2

// weight: exp(C*tanh(x/C)) = e^C * 2^(K2/(1 + 2^(x*K_PRE))); e^C cancels in softmax
#define K_PRE 0.5770780163555854f     //  2*log2(e)/C
#define K2   -14.426950408889634f     // -2*C*log2(e)

// Scratch (static device globals — no allocation allowed)
__device__ float g_rep[NM*ND];
__device__ float g_dhg[NM*N3];
__device__ float g_attn[NM*ND];
__device__ float g_p0[NM*ND];
__device__ float g_p1[NM*ND];
__device__ float g_p2[NM*ND];

#define BM 64
#define BN 64
#define BK 20        // 300 = 15 * 20; split-K3: 5 iters each
#define LPT 5        // loads/thread/tile: 64*20/256

typedef unsigned long long ull;

// ---------------- packed f32x2 helpers (FFMA2: 2x fp32 FMA rate) ------------
__device__ __forceinline__ ull pack2(float x, float y){
    ull r; asm("mov.b64 %0, {%1,%2};" : "=l"(r) : "f"(x), "f"(y)); return r;
}
__device__ __forceinline__ void ffma2(ull& d, ull a, ull b){
    asm("fma.rn.f32x2 %0, %1, %2, %0;" : "+l"(d) : "l"(a), "l"(b));
}
__device__ __forceinline__ float2 unpk(ull v){
    float2 r; asm("mov.b64 {%0,%1}, %2;" : "=f"(r.x), "=f"(r.y) : "l"(v)); return r;
}
__device__ __forceinline__ float ex2a(float x){ float y; asm("ex2.approx.f32 %0,%1;" : "=f"(y):"f"(x)); return y; }
__device__ __forceinline__ float rcpa(float x){ float y; asm("rcp.approx.f32 %0,%1;" : "=f"(y):"f"(x)); return y; }

// weight from precomputed pd=2^(dep'), ph=2^(head'): 4 instr, 2 MUFU
__device__ __forceinline__ float wfun2(float pd, float ph)
{
    float r = rcpa(fmaf(pd, ph, 1.f));
    return ex2a(K2 * r);
}

// 64x64 tile GEMM, C[m,n] += A[m,k]*W[n,k]. Double-buffered smem (R3-proven).
__device__ __forceinline__ void gemm_core(const float* __restrict__ A,
                                          const float* __restrict__ W,
                                          int m0, int n0, int kstart, int niter,
                                          ull (&acc)[4][2])
{
    __shared__ __align__(16) float As[2][BK][BM+4];
    __shared__ __align__(16) float Bs[2][BK][BN+4];
    const int tid = threadIdx.x;
    const int tx = tid & 15, ty = tid >> 4;

    #pragma unroll
    for (int e = 0; e < LPT; ++e) {
        int idx = tid + e*256;
        int r = idx / BK, c = idx - r*BK;
        As[0][c][r] = A[(m0 + r)*NK + kstart + c];
        int gn = n0 + r;
        Bs[0][c][r] = (gn < ND) ? W[gn*NK + kstart + c] : 0.f;
    }
    __syncthreads();

    int buf = 0;
    for (int it = 0; it < niter; ++it) {
        const bool has_next = (it + 1 < niter);
        float ra[LPT], rb[LPT];
        if (has_next) {
            int kn = kstart + (it + 1)*BK;
            #pragma unroll
            for (int e = 0; e < LPT; ++e) {
                int idx = tid + e*256;
                int r = idx / BK, c = idx - r*BK;
                ra[e] = A[(m0 + r)*NK + kn + c];
                int gn = n0 + r;
                rb[e] = (gn < ND) ? W[gn*NK + kn + c] : 0.f;
            }
        }
        #pragma unroll
        for (int k = 0; k < BK; ++k) {
            const float4 af = *(const float4*)&As[buf][k][ty*4];
            const ull b0 = *(const ull*)&Bs[buf][k][tx*4];
            const ull b1 = *(const ull*)&Bs[buf][k][tx*4 + 2];
            ull a0 = pack2(af.x, af.x);
            ull a1 = pack2(af.y, af.y);
            ull a2 = pack2(af.z, af.z);
            ull a3 = pack2(af.w, af.w);
            ffma2(acc[0][0], a0, b0); ffma2(acc[0][1], a0, b1);
            ffma2(acc[1][0], a1, b0); ffma2(acc[1][1], a1, b1);
            ffma2(acc[2][0], a2, b0); ffma2(acc[2][1], a2, b1);
            ffma2(acc[3][0], a3, b0); ffma2(acc[3][1], a3, b1);
        }
        if (has_next) {
            __syncthreads();
            #pragma unroll
            for (int e = 0; e < LPT; ++e) {
                int idx = tid + e*256;
                int r = idx / BK, c = idx - r*BK;
                As[buf^1][c][r] = ra[e];
                Bs[buf^1][c][r] = rb[e];
            }
            __syncthreads();
            buf ^= 1;
        }
    }
}

__device__ __forceinline__ void store_partial(float* __restrict__ dst,
                                              ull (&acc)[4][2], int m0, int n0)
{
    const int tx = threadIdx.x & 15, ty = threadIdx.x >> 4;
    #pragma unroll
    for (int p = 0; p < 4; ++p) {
        int m = m0 + ty*4 + p;
        #pragma unroll
        for (int qq = 0; qq < 2; ++qq) {
            float2 v = unpk(acc[p][qq]);
            int n = n0 + tx*4 + qq*2;
            if (n < ND)     dst[m*ND + n]     = v.x;
            if (n + 1 < ND) dst[m*ND + n + 1] = v.y;
        }
    }
}

// ---- P1: rep partial GEMM, split-K3 (z: k in [100z, 100z+100), 5 iters) ----
__global__ void __launch_bounds__(256)
gemm_rep_split(const float* __restrict__ A, const float* __restrict__ W)
{
    const int m0 = blockIdx.y * BM, n0 = blockIdx.x * BN;
    const int z = blockIdx.z;
    float* __restrict__ dst = (z == 0) ? g_p0 : ((z == 1) ? g_p1 : g_p2);
    ull acc[4][2] = {};
    gemm_core(A, W, m0, n0, z*100, 5, acc);
    store_partial(dst, acc, m0, n0);
}

// ---- P1b: g_rep = elu(p0 + p1 + p2 + b_fc) ---------------------------------
__global__ void __launch_bounds__(256)
finish_rep(const float* __restrict__ bias)
{
    int idx = blockIdx.x * 256 + threadIdx.x;
    if (idx >= NM*ND) return;
    int n = idx % ND;
    float v = g_p0[idx] + g_p1[idx] + g_p2[idx] + bias[n];
    g_rep[idx] = (v > 0.f) ? v : expm1f(v);
}

// ---- P2: pd/ph/gate1 GEMM (z selects matrix; pd,ph stored as 2^(·K_PRE)) ---
__global__ void __launch_bounds__(256)
gemm_triple(const float* __restrict__ W1, const float* __restrict__ W2,
            const float* __restrict__ Wf1, const float* __restrict__ b1,
            const float* __restrict__ bf)
{
    const int m0 = blockIdx.y * BM, n0 = blockIdx.x * BN;
    const int z = blockIdx.z;
    const float* W = (z == 0) ? W1 : ((z == 1) ? W2 : Wf1);
    ull acc[4][2] = {};
    gemm_core(g_rep, W, m0, n0, 0, 15, acc);
    const int tx = threadIdx.x & 15, ty = threadIdx.x >> 4;
    #pragma unroll
    for (int p = 0; p < 4; ++p) {
        int m = m0 + ty*4 + p;
        #pragma unroll
        for (int qq = 0; qq < 2; ++qq) {
            float2 v = unpk(acc[p][qq]);
            int n = n0 + tx*4 + qq*2;
            #pragma unroll
            for (int h = 0; h < 2; ++h) {
                int nn = n + h;
                if (nn < ND) {
                    float val = (h == 0) ? v.x : v.y;
                    if (z == 0)      val = ex2a(val * K_PRE);              // pd
                    else if (z == 1) val = ex2a((val + b1[nn]) * K_PRE);   // ph
                    else             val += bf[nn];                        // g1
                    g_dhg[m*N3 + z*ND + nn] = val;
                }
            }
        }
    }
}

// ---- P3: attention (IG=2, compacted valid-j list, j x2 unroll) -------------
__global__ void __launch_bounds__(320)
attn_kernel(const int* __restrict__ rmask)
{
    const int b = blockIdx.y;
    const int i0 = blockIdx.x * IG;
    const int t = threadIdx.x;

    __shared__ __align__(8) int jlist[NS];
    __shared__ int wcnt[8];
    __shared__ int nvalid_s;

    bool v = false;
    unsigned bal = 0;
    if (t < NS) {
        v = (t > i0) && (rmask[b*NS + t] != 0);
        bal = __ballot_sync(0xFFFFFFFFu, v);
        if ((t & 31) == 0) wcnt[t >> 5] = __popc(bal);
    }
    __syncthreads();
    if (t == 0) {
        int a = 0;
        #pragma unroll
        for (int k = 0; k < 8; ++k) { int c = wcnt[k]; wcnt[k] = a; a += c; }
        nvalid_s = a;
    }
    __syncthreads();
    if (t < NS && v) {
        int pos = wcnt[t >> 5] + __popc(bal & ((1u << (t & 31)) - 1u));
        jlist[pos] = t;
    }
    __syncthreads();

    const int nvalid = nvalid_s;
    if (t >= ND) return;

    const float ph0 = g_dhg[(size_t)(b*NS + i0    )*N3 + ND + t];
    const float ph1 = g_dhg[(size_t)(b*NS + i0 + 1)*N3 + ND + t];
    const float* __restrict__ pd_base  = g_dhg + (size_t)(b*NS)*N3 + t;
    const float* __restrict__ rep_base = g_rep + (size_t)(b*NS)*ND + t;

    float s0 = 0.f, w0 = 0.f, s1 = 0.f, w1 = 0.f;
    int idx = 0;
    for (; idx + 2 <= nvalid; idx += 2) {
        int2 jj = *(const int2*)&jlist[idx];
        float pd0 = pd_base[jj.x*N3], pd1 = pd_base[jj.y*N3];
        float rv0 = rep_base[jj.x*ND], rv1 = rep_base[jj.y*ND];
        float e00 = wfun2(pd0, ph0);
        float e01 = wfun2(pd1, ph0);
        float e10 = wfun2(pd0, ph1);
        float e11 = wfun2(pd1, ph1);
        s0 += e00 + e01;
        w0 = fmaf(e00, rv0, fmaf(e01, rv1, w0));
        s1 += e10 + e11;
        w1 = fmaf(e10, rv0, fmaf(e11, rv1, w1));
    }
    if (idx < nvalid) {
        int j0 = jlist[idx];
        float pd0 = pd_base[j0*N3];
        float rv0 = rep_base[j0*ND];
        float e00 = wfun2(pd0, ph0);
        float e10 = wfun2(pd0, ph1);
        s0 += e00;  w0 = fmaf(e00, rv0, w0);
        s1 += e10;  w1 = fmaf(e10, rv0, w1);
    }
    // i1 = i0+1 must exclude j == i0+1 (only possibly-invalid entry = jlist[0])
    if (nvalid > 0 && jlist[0] == i0 + 1) {
        float pd0 = pd_base[(i0 + 1)*N3];
        float rv0 = rep_base[(i0 + 1)*ND];
        float e10 = wfun2(pd0, ph1);
        s1 -= e10;  w1 = fmaf(-e10, rv0, w1);
    }
    float d0 = s0 + ((s0 == 0.f) ? 1.f : 0.f) + 1e-20f;
    float d1 = s1 + ((s1 == 0.f) ? 1.f : 0.f) + 1e-20f;
    g_attn[(size_t)(b*NS + i0    )*ND + t] = w0 / d0;
    g_attn[(size_t)(b*NS + i0 + 1)*ND + t] = w1 / d1;
}

// ---- P4: attn @ W_f2^T, split-K3 partials ----------------------------------
__global__ void __launch_bounds__(256)
gemm_final_split(const float* __restrict__ Wf2)
{
    const int m0 = blockIdx.y * BM, n0 = blockIdx.x * BN;
    const int z = blockIdx.z;
    float* __restrict__ dst = (z == 0) ? g_p0 : ((z == 1) ? g_p1 : g_p2);
    ull acc[4][2] = {};
    gemm_core(g_attn, Wf2, m0, n0, z*100, 5, acc);
    store_partial(dst, acc, m0, n0);
}

// ---- P4b: gate + blend + mask ----------------------------------------------
__global__ void __launch_bounds__(256)
final_epi(const int* __restrict__ rmask, float* __restrict__ out)
{
    int idx = blockIdx.x * 256 + threadIdx.x;
    if (idx >= NM*ND) return;
    int m = idx / ND, n = idx - m*ND;
    float vv = g_p0[idx] + g_p1[idx] + g_p2[idx] + g_dhg[m*N3 + 2*ND + n];
    float gate = 1.f / (1.f + __expf(-vv));
    float r = g_rep[idx];
    float a = g_attn[idx];
    out[idx] = (gate*r + (1.f - gate)*a) * (float)rmask[m];
}

extern "C" void kernel_launch(void* const* d_in, const int* in_sizes, int n_in,
                              void* d_out, int out_size)
{
    const float* inputs = (const float*)d_in[0];
    const int*   rmask  = (const int*)d_in[1];
    const float* W_fc   = (const float*)d_in[2];
    const float* b_fc   = (const float*)d_in[3];
    const float* W1     = (const float*)d_in[4];
    const float* W2     = (const float*)d_in[5];
    const float* b1     = (const float*)d_in[6];
    const float* W_f1   = (const float*)d_in[7];
    const float* W_f2   = (const float*)d_in[8];
    const float* b_f    = (const float*)d_in[9];
    float* out = (float*)d_out;

    dim3 blk(256);
    const int eBlocks = (NM*ND + 255) / 256;

    gemm_rep_split  <<<dim3(5, 16, 3), blk>>>(inputs, W_fc);
    finish_rep      <<<eBlocks, blk>>>(b_fc);
    gemm_triple     <<<dim3(5, 16, 3), blk>>>(W1, W2, W_f1, b1, b_f);
    attn_kernel     <<<dim3(NS/IG, NB), 320>>>(rmask);
    gemm_final_split<<<dim3(5, 16, 3), blk>>>(W_f2);
    final_epi       <<<eBlocks, blk>>>(rmask, out);
}